// round 12
// baseline (speedup 1.0000x reference)
#include <cuda_runtime.h>
#include <cuda_bf16.h>
#include <cstdint>
#include <stdint.h>
#include <math.h>

#define N 8192
#define D 64
#define LAM 0.5f
#define EPS 1e-8f
#define NT 64           // N / 128 tiles
#define NPAIRS 2080     // NT*(NT+1)/2
#define NWORDS (N / 32) // 256 bitmask words per row

// ---------------- device scratch ----------------
__device__ uint16_t g_zn_mp[N * 32];     // e4m3-packed normalized rows (64 B/row)
__device__ uint16_t g_zn_sc[N * 32];
__device__ unsigned g_posbits[N * NWORDS];  // 8 MB row-major pos bitmask
__device__ float g_prow_sum[NT][N];
__device__ float g_prow_pos[NT][N];
__device__ float g_pcol_sum[NT][N];
__device__ float g_pcol_pos[NT][N];
__device__ float g_blocksum[32];

// exp(x/tau) via MUFU.EX2
__device__ __forceinline__ float exp_tau(float x) {
    float y = x * 1.80336880f;   // (1/0.8) * log2(e)
    float r;
    asm("ex2.approx.ftz.f32 %0, %1;" : "=f"(r) : "f"(y));
    return r;
}

// e4m3 m16n8k32 MMA (A row-major, B col-major, f32 accum)
__device__ __forceinline__ void mma_fp8(float* c, const uint4& a, const uint2& b) {
    asm volatile(
        "mma.sync.aligned.m16n8k32.row.col.f32.e4m3.e4m3.f32 "
        "{%0,%1,%2,%3}, {%4,%5,%6,%7}, {%8,%9}, {%0,%1,%2,%3};"
        : "+f"(c[0]), "+f"(c[1]), "+f"(c[2]), "+f"(c[3])
        : "r"(a.x), "r"(a.y), "r"(a.z), "r"(a.w), "r"(b.x), "r"(b.y));
}

// ---------------- kernel 1: normalize + quantize to e4m3 ----------------
__global__ void normalize_kernel(const float* __restrict__ zmp,
                                 const float* __restrict__ zsc) {
    int gwarp = (blockIdx.x * blockDim.x + threadIdx.x) >> 5;
    int lane = threadIdx.x & 31;
    const float* src;
    uint16_t* dst;
    if (gwarp < N) {
        src = zmp + (size_t)gwarp * D;
        dst = g_zn_mp + (size_t)gwarp * 32;
    } else {
        src = zsc + (size_t)(gwarp - N) * D;
        dst = g_zn_sc + (size_t)(gwarp - N) * 32;
    }
    float2 v = *(const float2*)(src + 2 * lane);
    float s = v.x * v.x + v.y * v.y;
#pragma unroll
    for (int off = 16; off > 0; off >>= 1)
        s += __shfl_xor_sync(0xFFFFFFFF, s, off);
    float inv = rsqrtf(s);
    uint16_t packed;
    asm("cvt.rn.satfinite.e4m3x2.f32 %0, %1, %2;"
        : "=h"(packed) : "f"(v.y * inv), "f"(v.x * inv));
    dst[lane] = packed;
}

// ---------------- kernel 1b: pack pos -> bitmask (pure streaming) ----------------
// one thread per output u32 word: reads one full 128B line (8 x LDG.128), packs 32 bits
__global__ void pack_kernel(const int* __restrict__ pos) {
    int idx = blockIdx.x * blockDim.x + threadIdx.x;  // 0 .. N*NWORDS-1
    const int4* src = (const int4*)(pos + (size_t)idx * 32);
    unsigned w = 0;
#pragma unroll
    for (int j = 0; j < 8; j++) {
        int4 v = __ldcs(src + j);
        w |= (unsigned)((v.x & 1) | ((v.y & 1) << 1) | ((v.z & 1) << 2) |
                        ((v.w & 1) << 3)) << (j * 4);
    }
    g_posbits[idx] = w;
}

// ---------------- kernel 2: symmetric-pair tile kernel (fp8 HMMA) ----------------
// smem: Afrag[2] 16K | Bfrag[2] 16K | Pbits 2K | Qbits 2K | reds 6K  = 43008 B
#define OFF_AF   0
#define OFF_BF   16384
#define OFF_PB   32768
#define OFF_QB   34816
#define OFF_RRS  36864
#define OFF_RRP  38912
#define OFF_RCS  40960
#define OFF_RCP  41984
#define SMEM_BYTES 43008

__global__ __launch_bounds__(256, 2)
void pair_kernel() {
    extern __shared__ char smem[];
    unsigned* Pbits = (unsigned*)(smem + OFF_PB);
    unsigned* Qbits = (unsigned*)(smem + OFF_QB);
    float* RedRowS = (float*)(smem + OFF_RRS);   // [128][4]
    float* RedRowP = (float*)(smem + OFF_RRP);   // [128][4]
    float* RedColS = (float*)(smem + OFF_RCS);   // [128][2]
    float* RedColP = (float*)(smem + OFF_RCP);   // [128][2]

    const int tid = threadIdx.x;
    const int lane = tid & 31;
    const int wid = tid >> 5;
    const int wm = wid >> 2;   // 0..1 : 64-row slab
    const int wn = wid & 3;    // 0..3 : 32-col slab
    const int q = lane >> 2, l4 = lane & 3;

    // triangular decode: blockIdx.x -> (b0, b1), b0 <= b1
    int b0 = 0, rem = blockIdx.x;
    while (rem >= NT - b0) { rem -= NT - b0; b0++; }
    int b1 = b0 + rem;

    // ==== CTA head: stage all 4 z tiles + both pos bit tiles ====
    {
        // pos bit tiles: threads 0-127 load P rows, 128-255 load Q rows (1 LDG.128 each)
        int r = tid & 127;
        int side = tid >> 7;
        int rb_ = side ? b1 : b0;
        int cb_ = side ? b0 : b1;
        uint4 bits = *(const uint4*)(g_posbits + (size_t)(rb_ * 128 + r) * NWORDS + cb_ * 4);

        // z tiles: phase t uses A=mp[t? b1:b0], B=sc[t? b0:b1]
#pragma unroll
        for (int t = 0; t < 2; t++) {
            const char* Azg = (const char*)g_zn_mp + (size_t)((t ? b1 : b0) * 128) * 64;
            const char* Bzg = (const char*)g_zn_sc + (size_t)((t ? b0 : b1) * 128) * 64;
            uint32_t* Af = (uint32_t*)(smem + OFF_AF + t * 8192);
            uint32_t* Bf = (uint32_t*)(smem + OFF_BF + t * 8192);
#pragma unroll
            for (int i = 0; i < 2; i++) {
                int idx = tid + i * 256;
                int m = idx >> 2, c = idx & 3;
                int ks = c >> 1, kh = c & 1;
                uint4 v = *(const uint4*)(Azg + m * 64 + c * 16);
                uint32_t* d = Af + (((ks * 8 + (m >> 4)) * 32 + (m & 7) * 4) * 4) +
                              ((m >> 3) & 1) + 2 * kh;
                d[0] = v.x; d[4] = v.y; d[8] = v.z; d[12] = v.w;
                uint4 w = *(const uint4*)(Bzg + m * 64 + c * 16);
                uint32_t* e = Bf + (((ks * 16 + (m >> 3)) * 32 + (m & 7) * 4) * 2) + kh;
                e[0] = w.x; e[2] = w.y; e[4] = w.z; e[6] = w.w;
            }
        }

        unsigned* dstBits = side ? Qbits : Pbits;
        *(uint4*)(dstBits + r * 4) = bits;
    }
    __syncthreads();

    const int nphase = (b0 == b1) ? 1 : 2;

    for (int t = 0; t < nphase; t++) {
        const int rb = t ? b1 : b0;   // row tile (mp side)
        const int cb = t ? b0 : b1;   // col tile (sc side)
        const int RG = rb * 128, CG = cb * 128;
        const uint32_t* Asm32 = (const uint32_t*)(smem + OFF_AF + t * 8192);
        const uint32_t* Bsm32 = (const uint32_t*)(smem + OFF_BF + t * 8192);

        if (t == 1) __syncthreads();   // phase-0 finalize reads of reds complete

        // ---- fp8 tensor-core mainloop: warp tile 64x32, 2 K-steps of 32 ----
        float acc[4][4][4];
#pragma unroll
        for (int mt = 0; mt < 4; mt++)
#pragma unroll
            for (int nt = 0; nt < 4; nt++)
#pragma unroll
                for (int r = 0; r < 4; r++) acc[mt][nt][r] = 0.0f;

#pragma unroll
        for (int ks = 0; ks < 2; ks++) {
            uint4 a[4];
            uint2 b[4];
#pragma unroll
            for (int mt = 0; mt < 4; mt++)
                a[mt] = *(const uint4*)(Asm32 + ((ks * 8 + wm * 4 + mt) * 32 + lane) * 4);
#pragma unroll
            for (int nt = 0; nt < 4; nt++)
                b[nt] = *(const uint2*)(Bsm32 + ((ks * 16 + wn * 4 + nt) * 32 + lane) * 2);
#pragma unroll
            for (int mt = 0; mt < 4; mt++)
#pragma unroll
                for (int nt = 0; nt < 4; nt++)
                    mma_fp8(acc[mt][nt], a[mt], b[nt]);
        }

        // ---- epilogue: MUFU exp + bitmask pos pairing + partial reductions ----
        const unsigned* rowB = t ? Qbits : Pbits;   // bits[r][c] of pos(rb,cb)
        const unsigned* colB = t ? Pbits : Qbits;   // bits[c][r] of pos(cb,rb)

        unsigned cw[4][2][2];
#pragma unroll
        for (int nt = 0; nt < 4; nt++)
#pragma unroll
            for (int p = 0; p < 2; p++) {
                int c = wn * 32 + nt * 8 + 2 * l4 + p;
#pragma unroll
                for (int ws = 0; ws < 2; ws++)
                    cw[nt][p][ws] = colB[c * 4 + wm * 2 + ws];
            }

        float rs[8], rp2[8];
        float cs[4][2], cp2[4][2];
#pragma unroll
        for (int nt = 0; nt < 4; nt++) { cs[nt][0] = cs[nt][1] = 0.f; cp2[nt][0] = cp2[nt][1] = 0.f; }

#pragma unroll
        for (int mt = 0; mt < 4; mt++) {
            const int wsel = (mt >= 2) ? 1 : 0;          // (rloc>=32)
#pragma unroll
            for (int half = 0; half < 2; half++) {
                int rloc = mt * 16 + q + 8 * half;        // 0..63 within slab
                int r = wm * 64 + rloc;
                int bitidx = (mt & 1) * 16 + q + 8 * half; // rloc & 31
                unsigned rw = rowB[r * 4 + wn];
                float rsum = 0.f, rpos = 0.f;
#pragma unroll
                for (int nt = 0; nt < 4; nt++) {
                    float v0 = exp_tau(acc[mt][nt][half * 2 + 0]);
                    float v1 = exp_tau(acc[mt][nt][half * 2 + 1]);
                    unsigned rbits = rw >> (nt * 8 + 2 * l4);
                    rsum += v0 + v1;
                    if (rbits & 1u) rpos += v0;
                    if (rbits & 2u) rpos += v1;
                    cs[nt][0] += v0;
                    cs[nt][1] += v1;
                    if ((cw[nt][0][wsel] >> bitidx) & 1u) cp2[nt][0] += v0;
                    if ((cw[nt][1][wsel] >> bitidx) & 1u) cp2[nt][1] += v1;
                }
                rsum += __shfl_xor_sync(0xFFFFFFFF, rsum, 1);
                rsum += __shfl_xor_sync(0xFFFFFFFF, rsum, 2);
                rpos += __shfl_xor_sync(0xFFFFFFFF, rpos, 1);
                rpos += __shfl_xor_sync(0xFFFFFFFF, rpos, 2);
                rs[mt * 2 + half] = rsum;
                rp2[mt * 2 + half] = rpos;
            }
        }
#pragma unroll
        for (int nt = 0; nt < 4; nt++)
#pragma unroll
            for (int p = 0; p < 2; p++) {
                float v = cs[nt][p];
                v += __shfl_xor_sync(0xFFFFFFFF, v, 4);
                v += __shfl_xor_sync(0xFFFFFFFF, v, 8);
                v += __shfl_xor_sync(0xFFFFFFFF, v, 16);
                cs[nt][p] = v;
                float w = cp2[nt][p];
                w += __shfl_xor_sync(0xFFFFFFFF, w, 4);
                w += __shfl_xor_sync(0xFFFFFFFF, w, 8);
                w += __shfl_xor_sync(0xFFFFFFFF, w, 16);
                cp2[nt][p] = w;
            }

        if (l4 == 0) {
#pragma unroll
            for (int mt = 0; mt < 4; mt++)
#pragma unroll
                for (int half = 0; half < 2; half++) {
                    int r = wm * 64 + mt * 16 + q + 8 * half;
                    RedRowS[r * 4 + wn] = rs[mt * 2 + half];
                    RedRowP[r * 4 + wn] = rp2[mt * 2 + half];
                }
        }
        if (lane < 4) {
#pragma unroll
            for (int nt = 0; nt < 4; nt++)
#pragma unroll
                for (int p = 0; p < 2; p++) {
                    int c = wn * 32 + nt * 8 + 2 * lane + p;
                    RedColS[c * 2 + wm] = cs[nt][p];
                    RedColP[c * 2 + wm] = cp2[nt][p];
                }
        }
        __syncthreads();

        if (tid < 128) {
            float s = RedRowS[tid * 4 + 0] + RedRowS[tid * 4 + 1] +
                      RedRowS[tid * 4 + 2] + RedRowS[tid * 4 + 3];
            float sp = RedRowP[tid * 4 + 0] + RedRowP[tid * 4 + 1] +
                       RedRowP[tid * 4 + 2] + RedRowP[tid * 4 + 3];
            g_prow_sum[cb][RG + tid] = s;
            g_prow_pos[cb][RG + tid] = sp;
            float c = RedColS[tid * 2 + 0] + RedColS[tid * 2 + 1];
            float cp = RedColP[tid * 2 + 0] + RedColP[tid * 2 + 1];
            g_pcol_sum[rb][CG + tid] = c;
            g_pcol_pos[rb][CG + tid] = cp;
        }
    }
}

// ---------------- kernel 3: per-index log terms + block reduction ----------------
__global__ void reduce_kernel() {
    int i = blockIdx.x * 256 + threadIdx.x;
    float rs = 0.f, rp = 0.f, cs = 0.f, cp = 0.f;
#pragma unroll
    for (int t = 0; t < NT; t++) {
        rs += g_prow_sum[t][i];
        rp += g_prow_pos[t][i];
        cs += g_pcol_sum[t][i];
        cp += g_pcol_pos[t][i];
    }
    float contrib = LAM * (logf(rp) - logf(rs + EPS)) +
                    (1.0f - LAM) * (logf(cp) - logf(cs + EPS));
#pragma unroll
    for (int off = 16; off > 0; off >>= 1)
        contrib += __shfl_xor_sync(0xFFFFFFFF, contrib, off);
    __shared__ float ws[8];
    int lane = threadIdx.x & 31, warp = threadIdx.x >> 5;
    if (lane == 0) ws[warp] = contrib;
    __syncthreads();
    if (warp == 0) {
        float v = (lane < 8) ? ws[lane] : 0.0f;
#pragma unroll
        for (int off = 4; off > 0; off >>= 1)
            v += __shfl_xor_sync(0xFFFFFFFF, v, off);
        if (lane == 0) g_blocksum[blockIdx.x] = v;
    }
}

__global__ void final_kernel(float* __restrict__ out) {
    float v = g_blocksum[threadIdx.x];
#pragma unroll
    for (int off = 16; off > 0; off >>= 1)
        v += __shfl_xor_sync(0xFFFFFFFF, v, off);
    if (threadIdx.x == 0) out[0] = -v * (1.0f / (float)N);
}

// ---------------- launch ----------------
extern "C" void kernel_launch(void* const* d_in, const int* in_sizes, int n_in,
                              void* d_out, int out_size) {
    const float* z_mp = (const float*)d_in[0];
    const float* z_sc = (const float*)d_in[1];
    const int* pos = (const int*)d_in[2];
    float* out = (float*)d_out;

    cudaFuncSetAttribute(pair_kernel, cudaFuncAttributeMaxDynamicSharedMemorySize,
                         SMEM_BYTES);

    normalize_kernel<<<2 * N / 8, 256>>>(z_mp, z_sc);
    pack_kernel<<<N * NWORDS / 256, 256>>>(pos);
    pair_kernel<<<NPAIRS, 256, SMEM_BYTES>>>();
    reduce_kernel<<<N / 256, 256>>>();
    final_kernel<<<1, 32>>>(out);
}

// round 13
// speedup vs baseline: 1.4064x; 1.4064x over previous
#include <cuda_runtime.h>
#include <cuda_bf16.h>
#include <cstdint>
#include <stdint.h>
#include <math.h>

#define N 8192
#define D 64
#define LAM 0.5f
#define EPS 1e-8f
#define NT 64           // N / 128 tiles
#define NPAIRS 2080     // NT*(NT+1)/2

// ---------------- device scratch ----------------
__device__ uint16_t g_zn_mp[N * 32];   // e4m3-packed normalized rows (64 B/row)
__device__ uint16_t g_zn_sc[N * 32];
__device__ float g_prow_sum[NT][N];
__device__ float g_prow_pos[NT][N];
__device__ float g_pcol_sum[NT][N];
__device__ float g_pcol_pos[NT][N];
__device__ float g_blocksum[256];

// exp(x/tau) via MUFU.EX2
__device__ __forceinline__ float exp_tau(float x) {
    float y = x * 1.80336880f;   // (1/0.8) * log2(e)
    float r;
    asm("ex2.approx.ftz.f32 %0, %1;" : "=f"(r) : "f"(y));
    return r;
}

// e4m3 m16n8k32 MMA (A row-major, B col-major, f32 accum)
__device__ __forceinline__ void mma_fp8(float* c, const uint4& a, const uint2& b) {
    asm volatile(
        "mma.sync.aligned.m16n8k32.row.col.f32.e4m3.e4m3.f32 "
        "{%0,%1,%2,%3}, {%4,%5,%6,%7}, {%8,%9}, {%0,%1,%2,%3};"
        : "+f"(c[0]), "+f"(c[1]), "+f"(c[2]), "+f"(c[3])
        : "r"(a.x), "r"(a.y), "r"(a.z), "r"(a.w), "r"(b.x), "r"(b.y));
}

// ---------------- kernel 1: normalize + quantize to e4m3 ----------------
__global__ void normalize_kernel(const float* __restrict__ zmp,
                                 const float* __restrict__ zsc) {
    int gwarp = (blockIdx.x * blockDim.x + threadIdx.x) >> 5;
    int lane = threadIdx.x & 31;
    const float* src;
    uint16_t* dst;
    if (gwarp < N) {
        src = zmp + (size_t)gwarp * D;
        dst = g_zn_mp + (size_t)gwarp * 32;
    } else {
        src = zsc + (size_t)(gwarp - N) * D;
        dst = g_zn_sc + (size_t)(gwarp - N) * 32;
    }
    float2 v = *(const float2*)(src + 2 * lane);
    float s = v.x * v.x + v.y * v.y;
#pragma unroll
    for (int off = 16; off > 0; off >>= 1)
        s += __shfl_xor_sync(0xFFFFFFFF, s, off);
    float inv = rsqrtf(s);
    uint16_t packed;
    asm("cvt.rn.satfinite.e4m3x2.f32 %0, %1, %2;"
        : "=h"(packed) : "f"(v.y * inv), "f"(v.x * inv));
    dst[lane] = packed;
}

// ---------------- kernel 2: symmetric-pair tile kernel (fp8 HMMA) ----------------
#define SMEM_BYTES (8192 + 8192 + 2048 + 2048)

__global__ __launch_bounds__(256, 2)
void pair_kernel(const int* __restrict__ pos) {
    extern __shared__ char smem[];
    uint32_t* Asm32 = (uint32_t*)smem;
    uint32_t* Bsm32 = (uint32_t*)(smem + 8192);
    unsigned* Pbits = (unsigned*)(smem + 16384);
    unsigned* Qbits = (unsigned*)(smem + 16384 + 2048);
    // reduction overlay on Asm (after all frag reads complete)
    float* RedRowS = (float*)smem;          // [128][4]
    float* RedRowP = (float*)smem + 512;    // [128][4]
    float* RedColS = (float*)smem + 1024;   // [128][2]
    float* RedColP = (float*)smem + 1280;   // [128][2]

    const int tid = threadIdx.x;
    const int lane = tid & 31;
    const int wid = tid >> 5;
    const int wm = wid >> 2;   // 0..1 : 64-row slab
    const int wn = wid & 3;    // 0..3 : 32-col slab
    const int q = lane >> 2, l4 = lane & 3;

    // triangular decode: blockIdx.x -> (b0, b1), b0 <= b1
    int b0 = 0, rem = blockIdx.x;
    while (rem >= NT - b0) { rem -= NT - b0; b0++; }
    int b1 = b0 + rem;

    const int sh = (lane & 7) * 4;
    const int widx = lane >> 3;
    const int* Pbase = pos + (size_t)(b0 * 128 + wid) * N + b1 * 128 + lane * 4;
    const int* Qbase = pos + (size_t)(b1 * 128 + wid) * N + b0 * 128 + lane * 4;

    // ==== CTA head: prefetch phase-0 z (issued first) + batched pos staging ====
    {
        const char* Azg0 = (const char*)g_zn_mp + (size_t)(b0 * 128) * 64;
        const char* Bzg0 = (const char*)g_zn_sc + (size_t)(b1 * 128) * 64;
        uint4 zva[2], zvb[2];
#pragma unroll
        for (int i = 0; i < 2; i++) {
            int idx = tid + i * 256;
            int m = idx >> 2, c = idx & 3;
            zva[i] = *(const uint4*)(Azg0 + m * 64 + c * 16);
            zvb[i] = *(const uint4*)(Bzg0 + m * 64 + c * 16);
        }

        int4 pb[8], qb[8];
        // pos batch 1: 16 independent streaming LDG.128 in flight
#pragma unroll
        for (int j = 0; j < 8; j++) {
            pb[j] = __ldcs((const int4*)(Pbase + (size_t)j * 8 * N));
            qb[j] = __ldcs((const int4*)(Qbase + (size_t)j * 8 * N));
        }

        // store z to smem frag layout (pos loads still in flight)
#pragma unroll
        for (int i = 0; i < 2; i++) {
            int idx = tid + i * 256;
            int m = idx >> 2, c = idx & 3;
            int ks = c >> 1, kh = c & 1;
            uint32_t* d = Asm32 + (((ks * 8 + (m >> 4)) * 32 + (m & 7) * 4) * 4) +
                          ((m >> 3) & 1) + 2 * kh;
            d[0] = zva[i].x; d[4] = zva[i].y; d[8] = zva[i].z; d[12] = zva[i].w;
            uint32_t* e = Bsm32 + (((ks * 16 + (m >> 3)) * 32 + (m & 7) * 4) * 2) + kh;
            e[0] = zvb[i].x; e[2] = zvb[i].y; e[4] = zvb[i].z; e[6] = zvb[i].w;
        }

        // pack+store pos batch 1
#pragma unroll
        for (int j = 0; j < 8; j++) {
            int r = wid + j * 8;
            unsigned pw = ((pb[j].x & 1) | ((pb[j].y & 1) << 1) | ((pb[j].z & 1) << 2) |
                           ((pb[j].w & 1) << 3)) << sh;
            unsigned qw = ((qb[j].x & 1) | ((qb[j].y & 1) << 1) | ((qb[j].z & 1) << 2) |
                           ((qb[j].w & 1) << 3)) << sh;
            pw |= __shfl_xor_sync(0xFFFFFFFF, pw, 1);
            pw |= __shfl_xor_sync(0xFFFFFFFF, pw, 2);
            pw |= __shfl_xor_sync(0xFFFFFFFF, pw, 4);
            qw |= __shfl_xor_sync(0xFFFFFFFF, qw, 1);
            qw |= __shfl_xor_sync(0xFFFFFFFF, qw, 2);
            qw |= __shfl_xor_sync(0xFFFFFFFF, qw, 4);
            if ((lane & 7) == 0) {
                Pbits[r * 4 + widx] = pw;
                Qbits[r * 4 + widx] = qw;
            }
        }
        // pos batch 2
#pragma unroll
        for (int j = 0; j < 8; j++) {
            pb[j] = __ldcs((const int4*)(Pbase + (size_t)(j + 8) * 8 * N));
            qb[j] = __ldcs((const int4*)(Qbase + (size_t)(j + 8) * 8 * N));
        }
#pragma unroll
        for (int j = 0; j < 8; j++) {
            int r = wid + (j + 8) * 8;
            unsigned pw = ((pb[j].x & 1) | ((pb[j].y & 1) << 1) | ((pb[j].z & 1) << 2) |
                           ((pb[j].w & 1) << 3)) << sh;
            unsigned qw = ((qb[j].x & 1) | ((qb[j].y & 1) << 1) | ((qb[j].z & 1) << 2) |
                           ((qb[j].w & 1) << 3)) << sh;
            pw |= __shfl_xor_sync(0xFFFFFFFF, pw, 1);
            pw |= __shfl_xor_sync(0xFFFFFFFF, pw, 2);
            pw |= __shfl_xor_sync(0xFFFFFFFF, pw, 4);
            qw |= __shfl_xor_sync(0xFFFFFFFF, qw, 1);
            qw |= __shfl_xor_sync(0xFFFFFFFF, qw, 2);
            qw |= __shfl_xor_sync(0xFFFFFFFF, qw, 4);
            if ((lane & 7) == 0) {
                Pbits[r * 4 + widx] = pw;
                Qbits[r * 4 + widx] = qw;
            }
        }
    }
    __syncthreads();   // z frags + pos bits all visible

    const int nphase = (b0 == b1) ? 1 : 2;

    for (int t = 0; t < nphase; t++) {
        const int rb = t ? b1 : b0;   // row tile (mp side)
        const int cb = t ? b0 : b1;   // col tile (sc side)
        const int RG = rb * 128, CG = cb * 128;

        if (t == 1) {
            __syncthreads();   // finalize reads done; safe to overwrite frags/overlay
            const char* Azg = (const char*)g_zn_mp + (size_t)RG * 64;
            const char* Bzg = (const char*)g_zn_sc + (size_t)CG * 64;
#pragma unroll
            for (int i = 0; i < 2; i++) {
                int idx = tid + i * 256;
                int m = idx >> 2, c = idx & 3;
                int ks = c >> 1, kh = c & 1;
                uint4 v = *(const uint4*)(Azg + m * 64 + c * 16);
                uint32_t* d = Asm32 + (((ks * 8 + (m >> 4)) * 32 + (m & 7) * 4) * 4) +
                              ((m >> 3) & 1) + 2 * kh;
                d[0] = v.x; d[4] = v.y; d[8] = v.z; d[12] = v.w;
                uint4 w = *(const uint4*)(Bzg + m * 64 + c * 16);
                uint32_t* e = Bsm32 + (((ks * 16 + (m >> 3)) * 32 + (m & 7) * 4) * 2) + kh;
                e[0] = w.x; e[2] = w.y; e[4] = w.z; e[6] = w.w;
            }
            __syncthreads();
        }

        // ---- fp8 tensor-core mainloop: warp tile 64x32, 2 K-steps of 32 ----
        float acc[4][4][4];
#pragma unroll
        for (int mt = 0; mt < 4; mt++)
#pragma unroll
            for (int nt = 0; nt < 4; nt++)
#pragma unroll
                for (int r = 0; r < 4; r++) acc[mt][nt][r] = 0.0f;

#pragma unroll
        for (int ks = 0; ks < 2; ks++) {
            uint4 a[4];
            uint2 b[4];
#pragma unroll
            for (int mt = 0; mt < 4; mt++)
                a[mt] = *(const uint4*)(Asm32 + ((ks * 8 + wm * 4 + mt) * 32 + lane) * 4);
#pragma unroll
            for (int nt = 0; nt < 4; nt++)
                b[nt] = *(const uint2*)(Bsm32 + ((ks * 16 + wn * 4 + nt) * 32 + lane) * 2);
#pragma unroll
            for (int mt = 0; mt < 4; mt++)
#pragma unroll
                for (int nt = 0; nt < 4; nt++)
                    mma_fp8(acc[mt][nt], a[mt], b[nt]);
        }

        // ---- epilogue: MUFU exp + bitmask pos pairing + partial reductions ----
        const unsigned* rowB = t ? Qbits : Pbits;   // bits[r][c] of pos(rb,cb)
        const unsigned* colB = t ? Pbits : Qbits;   // bits[c][r] of pos(cb,rb)

        unsigned cw[4][2][2];
#pragma unroll
        for (int nt = 0; nt < 4; nt++)
#pragma unroll
            for (int p = 0; p < 2; p++) {
                int c = wn * 32 + nt * 8 + 2 * l4 + p;
#pragma unroll
                for (int ws = 0; ws < 2; ws++)
                    cw[nt][p][ws] = colB[c * 4 + wm * 2 + ws];
            }

        float rs[8], rp2[8];
        float cs[4][2], cp2[4][2];
#pragma unroll
        for (int nt = 0; nt < 4; nt++) { cs[nt][0] = cs[nt][1] = 0.f; cp2[nt][0] = cp2[nt][1] = 0.f; }

#pragma unroll
        for (int mt = 0; mt < 4; mt++) {
            const int wsel = (mt >= 2) ? 1 : 0;          // (rloc>=32)
#pragma unroll
            for (int half = 0; half < 2; half++) {
                int rloc = mt * 16 + q + 8 * half;        // 0..63 within slab
                int r = wm * 64 + rloc;
                int bitidx = (mt & 1) * 16 + q + 8 * half; // rloc & 31
                unsigned rw = rowB[r * 4 + wn];
                float rsum = 0.f, rpos = 0.f;
#pragma unroll
                for (int nt = 0; nt < 4; nt++) {
                    float v0 = exp_tau(acc[mt][nt][half * 2 + 0]);
                    float v1 = exp_tau(acc[mt][nt][half * 2 + 1]);
                    unsigned rbits = rw >> (nt * 8 + 2 * l4);
                    rsum += v0 + v1;
                    if (rbits & 1u) rpos += v0;
                    if (rbits & 2u) rpos += v1;
                    cs[nt][0] += v0;
                    cs[nt][1] += v1;
                    if ((cw[nt][0][wsel] >> bitidx) & 1u) cp2[nt][0] += v0;
                    if ((cw[nt][1][wsel] >> bitidx) & 1u) cp2[nt][1] += v1;
                }
                rsum += __shfl_xor_sync(0xFFFFFFFF, rsum, 1);
                rsum += __shfl_xor_sync(0xFFFFFFFF, rsum, 2);
                rpos += __shfl_xor_sync(0xFFFFFFFF, rpos, 1);
                rpos += __shfl_xor_sync(0xFFFFFFFF, rpos, 2);
                rs[mt * 2 + half] = rsum;
                rp2[mt * 2 + half] = rpos;
            }
        }
#pragma unroll
        for (int nt = 0; nt < 4; nt++)
#pragma unroll
            for (int p = 0; p < 2; p++) {
                float v = cs[nt][p];
                v += __shfl_xor_sync(0xFFFFFFFF, v, 4);
                v += __shfl_xor_sync(0xFFFFFFFF, v, 8);
                v += __shfl_xor_sync(0xFFFFFFFF, v, 16);
                cs[nt][p] = v;
                float w = cp2[nt][p];
                w += __shfl_xor_sync(0xFFFFFFFF, w, 4);
                w += __shfl_xor_sync(0xFFFFFFFF, w, 8);
                w += __shfl_xor_sync(0xFFFFFFFF, w, 16);
                cp2[nt][p] = w;
            }

        __syncthreads();   // frag reads done by all warps -> safe to overlay

        if (l4 == 0) {
#pragma unroll
            for (int mt = 0; mt < 4; mt++)
#pragma unroll
                for (int half = 0; half < 2; half++) {
                    int r = wm * 64 + mt * 16 + q + 8 * half;
                    RedRowS[r * 4 + wn] = rs[mt * 2 + half];
                    RedRowP[r * 4 + wn] = rp2[mt * 2 + half];
                }
        }
        if (lane < 4) {
#pragma unroll
            for (int nt = 0; nt < 4; nt++)
#pragma unroll
                for (int p = 0; p < 2; p++) {
                    int c = wn * 32 + nt * 8 + 2 * lane + p;
                    RedColS[c * 2 + wm] = cs[nt][p];
                    RedColP[c * 2 + wm] = cp2[nt][p];
                }
        }
        __syncthreads();

        if (tid < 128) {
            float s = RedRowS[tid * 4 + 0] + RedRowS[tid * 4 + 1] +
                      RedRowS[tid * 4 + 2] + RedRowS[tid * 4 + 3];
            float sp = RedRowP[tid * 4 + 0] + RedRowP[tid * 4 + 1] +
                       RedRowP[tid * 4 + 2] + RedRowP[tid * 4 + 3];
            g_prow_sum[cb][RG + tid] = s;
            g_prow_pos[cb][RG + tid] = sp;
            float c = RedColS[tid * 2 + 0] + RedColS[tid * 2 + 1];
            float cp = RedColP[tid * 2 + 0] + RedColP[tid * 2 + 1];
            g_pcol_sum[rb][CG + tid] = c;
            g_pcol_pos[rb][CG + tid] = cp;
        }
    }
}

// ---------------- kernel 3: parallel partial reduce + log terms ----------------
// grid 256, block 256: block covers 32 i's; warp w covers t-chunk [8w, 8w+8)
__global__ void reduce_kernel() {
    __shared__ float red[4][8][32];   // [stat][warp][lane] -> conflict-free
    int lane = threadIdx.x & 31, w = threadIdx.x >> 5;
    int i = blockIdx.x * 32 + lane;
    float rs = 0.f, rp = 0.f, cs = 0.f, cp = 0.f;
#pragma unroll
    for (int j = 0; j < 8; j++) {
        int t = w * 8 + j;
        rs += g_prow_sum[t][i];
        rp += g_prow_pos[t][i];
        cs += g_pcol_sum[t][i];
        cp += g_pcol_pos[t][i];
    }
    red[0][w][lane] = rs;
    red[1][w][lane] = rp;
    red[2][w][lane] = cs;
    red[3][w][lane] = cp;
    __syncthreads();
    if (w == 0) {
        float trs = 0.f, trp = 0.f, tcs = 0.f, tcp = 0.f;
#pragma unroll
        for (int k = 0; k < 8; k++) {
            trs += red[0][k][lane];
            trp += red[1][k][lane];
            tcs += red[2][k][lane];
            tcp += red[3][k][lane];
        }
        float contrib = LAM * (logf(trp) - logf(trs + EPS)) +
                        (1.0f - LAM) * (logf(tcp) - logf(tcs + EPS));
#pragma unroll
        for (int off = 16; off > 0; off >>= 1)
            contrib += __shfl_xor_sync(0xFFFFFFFF, contrib, off);
        if (lane == 0) g_blocksum[blockIdx.x] = contrib;
    }
}

__global__ void final_kernel(float* __restrict__ out) {
    int tid = threadIdx.x;
    float v = g_blocksum[tid];   // 256 block sums
#pragma unroll
    for (int off = 16; off > 0; off >>= 1)
        v += __shfl_xor_sync(0xFFFFFFFF, v, off);
    __shared__ float ws[8];
    int lane = tid & 31, warp = tid >> 5;
    if (lane == 0) ws[warp] = v;
    __syncthreads();
    if (warp == 0) {
        float s = (lane < 8) ? ws[lane] : 0.0f;
#pragma unroll
        for (int off = 4; off > 0; off >>= 1)
            s += __shfl_xor_sync(0xFFFFFFFF, s, off);
        if (lane == 0) out[0] = -s * (1.0f / (float)N);
    }
}

// ---------------- launch ----------------
extern "C" void kernel_launch(void* const* d_in, const int* in_sizes, int n_in,
                              void* d_out, int out_size) {
    const float* z_mp = (const float*)d_in[0];
    const float* z_sc = (const float*)d_in[1];
    const int* pos = (const int*)d_in[2];
    float* out = (float*)d_out;

    cudaFuncSetAttribute(pair_kernel, cudaFuncAttributeMaxDynamicSharedMemorySize,
                         SMEM_BYTES);

    normalize_kernel<<<2 * N / 8, 256>>>(z_mp, z_sc);
    pair_kernel<<<NPAIRS, 256, SMEM_BYTES>>>(pos);
    reduce_kernel<<<256, 256>>>();
    final_kernel<<<1, 256>>>(out);
}